// round 15
// baseline (speedup 1.0000x reference)
#include <cuda_runtime.h>
#include <cuda_bf16.h>
#include <stdint.h>
#include <math.h>

// ---------------- problem constants ----------------
#define B_    8
#define C_    384
#define C3_   1152
#define HW_   4096
#define HEADS_ 8
#define D_    48
#define DH_   24
#define D2_   32

// ---------------- device scratch ----------------
__device__ __align__(128) __nv_bfloat16  g_pre [(size_t)B_*C3_*HW_];   // qkv pre-dwconv (bf16)
__device__ __align__(128) __nv_bfloat16  g_v   [(size_t)B_*C_*HW_];    // v after dwconv (bf16)
__device__ __align__(128) __nv_bfloat16  g_wbf [C3_*C_];               // w_qkv in bf16
__device__ __align__(128) __nv_bfloat16  g_xT  [(size_t)B_*HW_*C_];    // x transposed [b,n,c] bf16
__device__ __align__(16) float g_r   [(size_t)B_*HEADS_*HW_];// r accum -> cmask (1MB)
__device__ float          g_wv  [D_];                   // avg_x @ w_vl (constant)
__device__ float          g_vbar[B_*HEADS_*D_];
__device__ __align__(16) float g_msp [(size_t)B_*HEADS_*HW_];
__device__ float          g_mch [B_*C_];

// ---------------- helpers ----------------
__device__ __forceinline__ float warpRedSum(float v){
#pragma unroll
    for (int o = 16; o > 0; o >>= 1) v += __shfl_xor_sync(0xffffffffu, v, o);
    return v;
}
__device__ __forceinline__ float warpRedMax(float v){
#pragma unroll
    for (int o = 16; o > 0; o >>= 1) v = fmaxf(v, __shfl_xor_sync(0xffffffffu, v, o));
    return v;
}
__device__ __forceinline__ float blockRedSum(float v, float* red){
    int tid = threadIdx.x, lane = tid & 31, wid = tid >> 5, nw = blockDim.x >> 5;
    __syncthreads();
    v = warpRedSum(v);
    if (lane == 0) red[wid] = v;
    __syncthreads();
    float r = (tid < nw) ? red[tid] : 0.f;
    if (wid == 0) r = warpRedSum(r);
    if (tid == 0) red[0] = r;
    __syncthreads();
    return red[0];
}
__device__ __forceinline__ float blockRedMax(float v, float* red){
    int tid = threadIdx.x, lane = tid & 31, wid = tid >> 5, nw = blockDim.x >> 5;
    __syncthreads();
    v = warpRedMax(v);
    if (lane == 0) red[wid] = v;
    __syncthreads();
    float r = (tid < nw) ? red[tid] : -1e30f;
    if (wid == 0) r = warpRedMax(r);
    if (tid == 0) red[0] = r;
    __syncthreads();
    return red[0];
}
// lean reductions for 16-warp (512-thread) blocks: 2 syncs each
__device__ __forceinline__ float2 blockRedSum2_16w(float2 v, float* red32){
    int lane = threadIdx.x & 31, wid = threadIdx.x >> 5;
    __syncthreads();
#pragma unroll
    for (int o = 16; o > 0; o >>= 1){
        v.x += __shfl_xor_sync(0xffffffffu, v.x, o);
        v.y += __shfl_xor_sync(0xffffffffu, v.y, o);
    }
    if (lane == 0){ red32[wid] = v.x; red32[wid + 16] = v.y; }
    __syncthreads();
    float sx = 0.f, sy = 0.f;
#pragma unroll
    for (int i = 0; i < 16; i++){ sx += red32[i]; sy += red32[i + 16]; }
    return make_float2(sx, sy);
}
__device__ __forceinline__ float blockRedSum_16w(float v, float* red32){
    int lane = threadIdx.x & 31, wid = threadIdx.x >> 5;
    __syncthreads();
    v = warpRedSum(v);
    if (lane == 0) red32[wid] = v;
    __syncthreads();
    float s = 0.f;
#pragma unroll
    for (int i = 0; i < 16; i++) s += red32[i];
    return s;
}
// exp(u) for tiny |u|: 4th-order Taylor, FMA-only
__device__ __forceinline__ float tiny_exp(float u){
    return 1.f + u * (1.f + u * (0.5f + u * (0.16666667f + u * 0.041666668f)));
}
__device__ __forceinline__ float sigmoidf(float z){
    return 1.f / (1.f + __expf(-z));
}

// ---------------- P0a: w_qkv -> bf16 ; zero g_r ; block 0: setup wv/vbar ----------------
__global__ void __launch_bounds__(256) prep_w_kernel(const float* __restrict__ w,
                                                     const float* __restrict__ w_al,
                                                     const float* __restrict__ w_vl)
{
    int gi = blockIdx.x * 256 + threadIdx.x;
    int i = gi * 2;
    if (i < C3_ * C_){
        float2 v = *(const float2*)(w + i);
        *(__nv_bfloat162*)(g_wbf + i) = __floats2bfloat162_rn(v.x, v.y);
    }
    const int NR = B_ * HEADS_ * HW_;           // 262144
    const int stride = gridDim.x * 256;
    for (int j = gi; j < NR; j += stride) g_r[j] = 0.f;

    if (blockIdx.x == 0){
        __shared__ float avg[24];
        const int tid = threadIdx.x;
        if (tid < 24){
            float s = 0.f;
            for (int d = 0; d < 48; d++) s += w_al[tid * 48 + d];
            avg[tid] = s * (1.f / 4096.f);
        }
        __syncthreads();
        if (tid == 0){
            float mx = -1e30f;
            for (int o = 0; o < 24; o++) mx = fmaxf(mx, avg[o]);
            float ssum = 0.f;
            for (int o = 0; o < 24; o++){ float ev = expf(avg[o] - mx); avg[o] = ev; ssum += ev; }
            float inv = 1.f / ssum;
            for (int o = 0; o < 24; o++) avg[o] *= inv;
        }
        __syncthreads();
        if (tid < 48){
            float s = 0.f;
            for (int o = 0; o < 24; o++) s += avg[o] * w_vl[o * 48 + tid];
            g_wv[tid] = s;
        }
        for (int j = tid; j < B_ * HEADS_ * D_; j += 256) g_vbar[j] = 0.f;
    }
}

// ---------------- P0b: x [b,c,n] fp32 -> xT [b,n,c] bf16 ----------------
__global__ void __launch_bounds__(256) prep_x_kernel(const float* __restrict__ x)
{
    __shared__ float tile[32][33];
    const int b  = blockIdx.z;
    const int n0 = blockIdx.x * 32;
    const int c0 = blockIdx.y * 32;
    const int tid = threadIdx.x, lane = tid & 31, w = tid >> 5;

#pragma unroll
    for (int r = 0; r < 4; r++){
        int c = w + r * 8;
        tile[c][lane] = x[((size_t)b * C_ + c0 + c) * HW_ + n0 + lane];
    }
    __syncthreads();
#pragma unroll
    for (int r = 0; r < 4; r++){
        int idx = tid + r * 256;
        int n = idx >> 5, c = idx & 31;
        g_xT[((size_t)b * HW_ + n0 + n) * C_ + c0 + c] = __float2bfloat16(tile[c][n]);
    }
}

// ---------------- P1: conv1x1 GEMM, bf16 mma.sync, 3-stage cp.async, upfront frags ----------------
__device__ __forceinline__ void mma16816(float* c, const uint32_t* a, const uint32_t* b){
    asm volatile(
        "mma.sync.aligned.m16n8k16.row.col.f32.bf16.bf16.f32 "
        "{%0,%1,%2,%3},{%4,%5,%6,%7},{%8,%9},{%0,%1,%2,%3};"
        : "+f"(c[0]), "+f"(c[1]), "+f"(c[2]), "+f"(c[3])
        : "r"(a[0]), "r"(a[1]), "r"(a[2]), "r"(a[3]), "r"(b[0]), "r"(b[1]));
}
__device__ __forceinline__ void ldsm_x4(uint32_t& r0, uint32_t& r1, uint32_t& r2, uint32_t& r3, uint32_t addr){
    asm volatile("ldmatrix.sync.aligned.m8n8.x4.shared.b16 {%0,%1,%2,%3},[%4];"
                 : "=r"(r0), "=r"(r1), "=r"(r2), "=r"(r3) : "r"(addr));
}
__device__ __forceinline__ void ldsm_x2(uint32_t& r0, uint32_t& r1, uint32_t addr){
    asm volatile("ldmatrix.sync.aligned.m8n8.x2.shared.b16 {%0,%1},[%2];"
                 : "=r"(r0), "=r"(r1) : "r"(addr));
}
__device__ __forceinline__ void cp16(uint32_t saddr, const void* gptr){
    asm volatile("cp.async.cg.shared.global [%0],[%1],16;" :: "r"(saddr), "l"(gptr));
}
__device__ __forceinline__ void cp_commit(){ asm volatile("cp.async.commit_group;"); }

#define GSTR 40                        // bf16 elems per smem row (32 data + pad)
#define STAGE_BYTES (128 * GSTR * 2)   // per matrix per stage = 10240 B
#define GSTAGES 3
#define GSMEM_TOTAL (GSTAGES * 2 * STAGE_BYTES)   // 61440 B

__global__ void __launch_bounds__(256) gemm_qkv_kernel()
{
    extern __shared__ __align__(128) __nv_bfloat16 gsm[];

    const int b  = blockIdx.z;
    const int o0 = blockIdx.y * 128;
    const int n0 = blockIdx.x * 128;
    const int tid  = threadIdx.x;
    const int warp = tid >> 5, lane = tid & 31;
    const int wm = (warp >> 2) * 64;
    const int wn = (warp & 3) * 32;

    float acc[4][4][4];
#pragma unroll
    for (int i = 0; i < 4; i++)
#pragma unroll
        for (int j = 0; j < 4; j++)
#pragma unroll
            for (int q = 0; q < 4; q++) acc[i][j][q] = 0.f;

    const __nv_bfloat16* wg = g_wbf + (size_t)o0 * C_;
    const __nv_bfloat16* xg = g_xT + ((size_t)b * HW_ + n0) * C_;

    const int r0i = (tid      ) >> 2, c0i = ((tid      ) & 3) * 8;
    const int r1i = (tid + 256) >> 2, c1i = ((tid + 256) & 3) * 8;

    const uint32_t sm0 = (uint32_t)__cvta_generic_to_shared(gsm);

    auto stage = [&](int c){
        uint32_t sa = sm0 + (c % GSTAGES) * 2 * STAGE_BYTES;
        uint32_t sb = sa + STAGE_BYTES;
        int k0 = c * 32;
        cp16(sa + (r0i * GSTR + c0i) * 2, wg + (size_t)r0i * C_ + k0 + c0i);
        cp16(sa + (r1i * GSTR + c1i) * 2, wg + (size_t)r1i * C_ + k0 + c1i);
        cp16(sb + (r0i * GSTR + c0i) * 2, xg + (size_t)r0i * C_ + k0 + c0i);
        cp16(sb + (r1i * GSTR + c1i) * 2, xg + (size_t)r1i * C_ + k0 + c1i);
        cp_commit();
    };

    stage(0); stage(1); stage(2);

    const int aRow = (lane & 7) + ((lane >> 3) & 1) * 8;
    const int aKof = (lane >> 4) * 8;
    const int bRow = (lane & 7);
    const int bKof = ((lane >> 3) & 1) * 8;

    for (int c = 0; c < 12; c++){
        if (c < 10)       asm volatile("cp.async.wait_group 2;");
        else if (c == 10) asm volatile("cp.async.wait_group 1;");
        else              asm volatile("cp.async.wait_group 0;");
        __syncthreads();

        uint32_t sa = sm0 + (c % GSTAGES) * 2 * STAGE_BYTES;
        uint32_t sb = sa + STAGE_BYTES;

#pragma unroll
        for (int kk = 0; kk < 2; kk++){
            const int krow = kk * 16;
            uint32_t af[4][4], bf[4][2];
#pragma unroll
            for (int mi = 0; mi < 4; mi++){
                uint32_t addr = sa + ((wm + mi * 16 + aRow) * GSTR + krow + aKof) * 2;
                ldsm_x4(af[mi][0], af[mi][1], af[mi][2], af[mi][3], addr);
            }
#pragma unroll
            for (int ni = 0; ni < 4; ni++){
                uint32_t addr = sb + ((wn + ni * 8 + bRow) * GSTR + krow + bKof) * 2;
                ldsm_x2(bf[ni][0], bf[ni][1], addr);
            }
#pragma unroll
            for (int mi = 0; mi < 4; mi++)
#pragma unroll
                for (int ni = 0; ni < 4; ni++)
                    mma16816(acc[mi][ni], af[mi], bf[ni]);
        }
        __syncthreads();
        if (c < 9) stage(c + 3);
    }

    __nv_bfloat16* out = g_pre + ((size_t)b * C3_ + o0) * HW_ + n0;
#pragma unroll
    for (int mi = 0; mi < 4; mi++){
#pragma unroll
        for (int ni = 0; ni < 4; ni++){
            int r = wm + mi * 16 + (lane >> 2);
            int c = wn + ni * 8 + (lane & 3) * 2;
            *(__nv_bfloat162*)(out + (size_t)r * HW_ + c) =
                __floats2bfloat162_rn(acc[mi][ni][0], acc[mi][ni][1]);
            *(__nv_bfloat162*)(out + (size_t)(r + 8) * HW_ + c) =
                __floats2bfloat162_rn(acc[mi][ni][2], acc[mi][ni][3]);
        }
    }
}

// ---------------- P2: fused dwconv(q,k,v) — 512 threads, 8 outputs/thread ----------------
// register-sliding 3x3 stencil: thread = column x, 8 outputs along y.
__device__ __forceinline__ float conv_col8(const float* tile, const float* w9,
                                           int x, int ys, float* o8)
{
    const float* tp = tile + ys * 66 + x;
    float a0 = tp[0],  a1 = tp[1],  a2 = tp[2];
    float b0 = tp[66], b1 = tp[67], b2 = tp[68];
    float ss = 0.f;
#pragma unroll
    for (int j = 0; j < 8; j++){
        const float* tr = tp + 132 + j * 66;
        float c0 = tr[0], c1 = tr[1], c2 = tr[2];
        float o = w9[0]*a0 + w9[1]*a1 + w9[2]*a2
                + w9[3]*b0 + w9[4]*b1 + w9[5]*b2
                + w9[6]*c0 + w9[7]*c1 + w9[8]*c2;
        o8[j] = o;
        ss = fmaf(o, o, ss);
        a0 = b0; a1 = b1; a2 = b2;
        b0 = c0; b1 = c1; b2 = c2;
    }
    return ss;
}

__global__ void __launch_bounds__(512) dwfuse_kernel(const float* __restrict__ w_dw,
                                                     const float* __restrict__ temp,
                                                     const float* __restrict__ w_ar)
{
    __shared__ float tiles[3][66 * 66];   // q, k, v
    __shared__ float red32[32];
    const int blk = blockIdx.x;           // b*384 + ch, ch = h*48 + d
    const int b = blk / 384, ch = blk % 384;
    const int h = ch / 48, dd = ch % 48;
    const int tid = threadIdx.x;
    const int x = tid & 63, ys = (tid >> 6) * 8;   // 8 row-groups of 8

    // ---- single load phase: halo zero + interior for all 3 planes ----
    if (tid < 66){
#pragma unroll
        for (int p = 0; p < 3; p++){ tiles[p][tid] = 0.f; tiles[p][65 * 66 + tid] = 0.f; }
    } else if (tid < 130){
        int yy = tid - 66;
#pragma unroll
        for (int p = 0; p < 3; p++){ tiles[p][(yy + 1) * 66] = 0.f; tiles[p][(yy + 1) * 66 + 65] = 0.f; }
    }
#pragma unroll
    for (int p = 0; p < 3; p++){
        const __nv_bfloat162* in2 = (const __nv_bfloat162*)
            (g_pre + ((size_t)b * C3_ + p * C_ + ch) * HW_);
        float* t = tiles[p];
#pragma unroll
        for (int q = tid; q < 2048; q += 512){
            int y = q >> 5, x0 = (q & 31) * 2;
            float2 f = __bfloat1622float2(in2[q]);
            t[(y + 1) * 66 + x0 + 1] = f.x;
            t[(y + 1) * 66 + x0 + 2] = f.y;
        }
    }
    __syncthreads();   // sync 1 of 5

    // ---- v plane: conv -> g_v (streamed, no sync) ----
    {
        float w9[9];
#pragma unroll
        for (int j = 0; j < 9; j++) w9[j] = __ldg(w_dw + (2 * C_ + ch) * 9 + j);
        const float* tp = tiles[2] + ys * 66 + x;
        float a0 = tp[0],  a1 = tp[1],  a2 = tp[2];
        float b0 = tp[66], b1 = tp[67], b2 = tp[68];
        __nv_bfloat16* outp = g_v + (size_t)blk * HW_ + ys * 64 + x;
#pragma unroll
        for (int j = 0; j < 8; j++){
            const float* tr = tp + 132 + j * 66;
            float c0 = tr[0], c1 = tr[1], c2 = tr[2];
            float o = w9[0]*a0 + w9[1]*a1 + w9[2]*a2
                    + w9[3]*b0 + w9[4]*b1 + w9[5]*b2
                    + w9[6]*c0 + w9[7]*c1 + w9[8]*c2;
            outp[j * 64] = __float2bfloat16(o);
            a0 = b0; a1 = b1; a2 = b2;
            b0 = c0; b1 = c1; b2 = c2;
        }
    }

    // ---- q, k planes: conv to registers ----
    float qv[8], kv[8];
    float ssq, ssk;
    {
        float w9[9];
#pragma unroll
        for (int j = 0; j < 9; j++) w9[j] = __ldg(w_dw + ch * 9 + j);
        ssq = conv_col8(tiles[0], w9, x, ys, qv);
#pragma unroll
        for (int j = 0; j < 9; j++) w9[j] = __ldg(w_dw + (C_ + ch) * 9 + j);
        ssk = conv_col8(tiles[1], w9, x, ys, kv);
    }

    float2 ns = blockRedSum2_16w(make_float2(ssq, ssk), red32);  // syncs 2-3
    const float nq = fmaxf(sqrtf(ns.x), 1e-12f);
    const float nk = fmaxf(sqrtf(ns.y), 1e-12f);
    const float scale = __ldg(temp + h) / (nq * nk);

    // e = exp(s), row sum S_d, then accumulate coef*e into g_r
    float zs = 0.f;
#pragma unroll
    for (int j = 0; j < 8; j++){
        float e = tiny_exp(qv[j] * kv[j] * scale);
        qv[j] = e;
        zs += e;
    }
    zs = blockRedSum_16w(zs, red32);                             // syncs 4-5
    const float coef = __ldg(w_ar + dd) / zs;

    float* rr = g_r + ((size_t)(b * HEADS_ + h)) * HW_ + ys * 64 + x;
#pragma unroll
    for (int j = 0; j < 8; j++)
        atomicAdd(rr + j * 64, coef * qv[j]);
}

// ---------------- P4: cmask = softmax_n(r), in place ----------------
__global__ void __launch_bounds__(512) softmax_r_kernel()
{
    __shared__ float red[32];
    const int bh = blockIdx.x, tid = threadIdx.x;
    float* r = g_r + (size_t)bh * HW_;

    float v[8];
    float m = -1e30f;
#pragma unroll
    for (int k = 0; k < 4; k++){
        float2 f = *(const float2*)(r + (tid + k * 512) * 2);
        v[2*k] = f.x; v[2*k+1] = f.y;
        m = fmaxf(m, fmaxf(f.x, f.y));
    }
    m = blockRedMax(m, red);
    float s = 0.f;
#pragma unroll
    for (int k = 0; k < 8; k++){ v[k] = __expf(v[k] - m); s += v[k]; }
    s = blockRedSum(s, red);
    const float inv = 1.f / s;
#pragma unroll
    for (int k = 0; k < 4; k++)
        *(float2*)(r + (tid + k * 512) * 2) = make_float2(v[2*k] * inv, v[2*k+1] * inv);
}

// ---------------- P5: vbar_d = sum_n cmask_n v_dn ; msp = sigmoid(sum_d wv_d v_dn) ----------------
// Grid (8, 64): 512 blocks, each covers 512 n-cols (2 per thread).
__global__ void __launch_bounds__(256) vz_kernel()
{
    __shared__ float cm[512];
    __shared__ float wv_s[48];
    __shared__ float vbar_s[48];
    const int bh = blockIdx.y;
    const int n0 = blockIdx.x * 512;
    const int tid = threadIdx.x, lane = tid & 31;

    if (tid < 48){ wv_s[tid] = g_wv[tid]; vbar_s[tid] = 0.f; }
    *(float2*)(cm + tid * 2) = *(const float2*)(g_r + (size_t)bh * HW_ + n0 + tid * 2);
    __syncthreads();

    float zz0 = 0.f, zz1 = 0.f;
    const float c0 = cm[tid * 2], c1 = cm[tid * 2 + 1];
    const __nv_bfloat162* vb = (const __nv_bfloat162*)
        (g_v + ((size_t)bh * 48) * HW_ + n0);
    for (int d = 0; d < 48; d++){
        float2 f = __bfloat1622float2(vb[(size_t)d * (HW_ / 2) + tid]);
        const float wvd = wv_s[d];
        float dot = fmaf(c0, f.x, c1 * f.y);
        zz0 = fmaf(wvd, f.x, zz0);
        zz1 = fmaf(wvd, f.y, zz1);
        dot = warpRedSum(dot);
        if (lane == 0) atomicAdd(&vbar_s[d], dot);
    }
    __syncthreads();
    if (tid < 48) atomicAdd(&g_vbar[bh * 48 + tid], vbar_s[tid]);
    *(float2*)(g_msp + (size_t)bh * HW_ + n0 + tid * 2) =
        make_float2(sigmoidf(zz0), sigmoidf(zz1));
}

// ---------------- P6: ctx + MLP + LayerNorm -> channel gate ----------------
__global__ void __launch_bounds__(256) mlp_kernel(
    const float* __restrict__ w_vr,
    const float* __restrict__ w_up1, const float* __restrict__ b_up1,
    const float* __restrict__ ln_g,  const float* __restrict__ ln_b,
    const float* __restrict__ w_up2, const float* __restrict__ b_up2)
{
    __shared__ float vbar_s[384];
    __shared__ float ctx_s[192];
    __shared__ float t1[256];
    __shared__ float red[32];
    const int b = blockIdx.x, tid = threadIdx.x;

    for (int i = tid; i < 384; i += 256) vbar_s[i] = g_vbar[b * 384 + i];
    __syncthreads();
    if (tid < 192){
        int hh = tid / 24, o = tid % 24;
        float c = 0.f;
#pragma unroll
        for (int d = 0; d < 48; d++) c += w_vr[o * 48 + d] * vbar_s[hh * 48 + d];
        ctx_s[hh * 24 + o] = c;
    }
    __syncthreads();

    const int o = tid >> 3, hh = tid & 7;
    float t = b_up1[o];
#pragma unroll
    for (int p = 0; p < 24; p++) t += w_up1[o * 24 + p] * ctx_s[hh * 24 + p];

    float mu = blockRedSum(t, red) * (1.f / 256.f);
    float d = t - mu;
    float var = blockRedSum(d * d, red) * (1.f / 256.f);
    float tn = (t - mu) * rsqrtf(var + 1e-5f) * ln_g[o * 8 + hh] + ln_b[o * 8 + hh];
    t1[tid] = fmaxf(tn, 0.f);
    __syncthreads();

    for (int idx = tid; idx < 384; idx += 256){
        int dd = idx >> 3, h2 = idx & 7;
        float v = b_up2[dd];
#pragma unroll
        for (int oo = 0; oo < 32; oo++) v += w_up2[dd * 32 + oo] * t1[oo * 8 + h2];
        g_mch[b * 384 + dd * 8 + h2] = sigmoidf(v);
    }
}

// ---------------- P7: out = x * (mch[b,c] + sum_h w_proj[c,h]*msp[b,h,n]) ----------------
// Grid (16,4,8): block = 256 n-cols x 96 channels; msp in registers (1 col/thread).
__global__ void __launch_bounds__(256) final_kernel(
    const float* __restrict__ x, const float* __restrict__ w_proj,
    float* __restrict__ out)
{
    __shared__ float wp_s[96 * 8];
    __shared__ float mch_s[96];
    const int b  = blockIdx.z;
    const int n0 = blockIdx.x * 256;
    const int c0 = blockIdx.y * 96;
    const int tid = threadIdx.x;
    const int nn = n0 + tid;

    // msp for this thread's column, all 8 heads -> registers (coalesced LDG)
    float mh[8];
#pragma unroll
    for (int h = 0; h < 8; h++)
        mh[h] = g_msp[((size_t)(b * 8 + h)) * HW_ + nn];

    for (int i = tid; i < 768; i += 256) wp_s[i] = w_proj[c0 * 8 + i];
    if (tid < 96) mch_s[tid] = g_mch[b * 384 + c0 + tid];
    __syncthreads();

    for (int cc = 0; cc < 96; cc++){
        const float* wp = wp_s + cc * 8;
        float a = mch_s[cc];
#pragma unroll
        for (int h = 0; h < 8; h++) a = fmaf(wp[h], mh[h], a);
        size_t base = ((size_t)(b * 384 + c0 + cc)) * HW_ + nn;
        out[base] = x[base] * a;
    }
}

// ---------------- launcher ----------------
extern "C" void kernel_launch(void* const* d_in, const int* in_sizes, int n_in,
                              void* d_out, int out_size)
{
    const float* x      = (const float*)d_in[0];
    const float* w_qkv  = (const float*)d_in[1];
    const float* w_dw   = (const float*)d_in[2];
    const float* temp   = (const float*)d_in[3];
    const float* w_ar   = (const float*)d_in[4];
    const float* w_vr   = (const float*)d_in[5];
    const float* w_up1  = (const float*)d_in[6];
    const float* b_up1  = (const float*)d_in[7];
    const float* ln_g   = (const float*)d_in[8];
    const float* ln_b   = (const float*)d_in[9];
    const float* w_up2  = (const float*)d_in[10];
    const float* b_up2  = (const float*)d_in[11];
    const float* w_al   = (const float*)d_in[12];
    const float* w_vl   = (const float*)d_in[13];
    const float* w_proj = (const float*)d_in[14];
    float* out = (float*)d_out;

    cudaFuncSetAttribute(gemm_qkv_kernel,
                         cudaFuncAttributeMaxDynamicSharedMemorySize, GSMEM_TOTAL);

    prep_w_kernel<<<(C3_ * C_ / 2 + 255) / 256, 256>>>(w_qkv, w_al, w_vl);
    prep_x_kernel<<<dim3(128, 12, 8), 256>>>(x);
    gemm_qkv_kernel<<<dim3(32, 9, 8), 256, GSMEM_TOTAL>>>();
    dwfuse_kernel<<<B_ * C_, 512>>>(w_dw, temp, w_ar);
    softmax_r_kernel<<<64, 512>>>();
    vz_kernel<<<dim3(8, 64), 256>>>();
    mlp_kernel<<<B_, 256>>>(w_vr, w_up1, b_up1, ln_g, ln_b, w_up2, b_up2);
    final_kernel<<<dim3(16, 4, 8), 256>>>(x, w_proj, out);
}

// round 16
// speedup vs baseline: 1.0487x; 1.0487x over previous
#include <cuda_runtime.h>
#include <cuda_bf16.h>
#include <stdint.h>
#include <math.h>

// ---------------- problem constants ----------------
#define B_    8
#define C_    384
#define C3_   1152
#define HW_   4096
#define HEADS_ 8
#define D_    48
#define DH_   24
#define D2_   32

// ---------------- device scratch ----------------
__device__ __align__(128) __nv_bfloat16  g_pre [(size_t)B_*C3_*HW_];   // qkv pre-dwconv (bf16)
__device__ __align__(128) __nv_bfloat16  g_v   [(size_t)B_*C_*HW_];    // v after dwconv (bf16)
__device__ __align__(128) __nv_bfloat16  g_wbf [C3_*C_];               // w_qkv in bf16
__device__ __align__(128) __nv_bfloat16  g_xT  [(size_t)B_*HW_*C_];    // x transposed [b,n,c] bf16
__device__ __align__(16) float g_r   [(size_t)B_*HEADS_*HW_];// r accum -> cmask (1MB)
__device__ float          g_wv  [D_];                   // avg_x @ w_vl (constant)
__device__ float          g_vbar[B_*HEADS_*D_];
__device__ __align__(16) float g_msp [(size_t)B_*HEADS_*HW_];
__device__ float          g_mch [B_*C_];

// ---------------- helpers ----------------
__device__ __forceinline__ float warpRedSum(float v){
#pragma unroll
    for (int o = 16; o > 0; o >>= 1) v += __shfl_xor_sync(0xffffffffu, v, o);
    return v;
}
__device__ __forceinline__ float warpRedMax(float v){
#pragma unroll
    for (int o = 16; o > 0; o >>= 1) v = fmaxf(v, __shfl_xor_sync(0xffffffffu, v, o));
    return v;
}
__device__ __forceinline__ float blockRedSum(float v, float* red){
    int tid = threadIdx.x, lane = tid & 31, wid = tid >> 5, nw = blockDim.x >> 5;
    __syncthreads();
    v = warpRedSum(v);
    if (lane == 0) red[wid] = v;
    __syncthreads();
    float r = (tid < nw) ? red[tid] : 0.f;
    if (wid == 0) r = warpRedSum(r);
    if (tid == 0) red[0] = r;
    __syncthreads();
    return red[0];
}
__device__ __forceinline__ float blockRedMax(float v, float* red){
    int tid = threadIdx.x, lane = tid & 31, wid = tid >> 5, nw = blockDim.x >> 5;
    __syncthreads();
    v = warpRedMax(v);
    if (lane == 0) red[wid] = v;
    __syncthreads();
    float r = (tid < nw) ? red[tid] : -1e30f;
    if (wid == 0) r = warpRedMax(r);
    if (tid == 0) red[0] = r;
    __syncthreads();
    return red[0];
}
// lean reductions for 8-warp (256-thread) blocks: 2 syncs each
__device__ __forceinline__ float2 blockRedSum2_8w(float2 v, float* red16){
    int lane = threadIdx.x & 31, wid = threadIdx.x >> 5;
    __syncthreads();
#pragma unroll
    for (int o = 16; o > 0; o >>= 1){
        v.x += __shfl_xor_sync(0xffffffffu, v.x, o);
        v.y += __shfl_xor_sync(0xffffffffu, v.y, o);
    }
    if (lane == 0){ red16[wid] = v.x; red16[wid + 8] = v.y; }
    __syncthreads();
    float sx = 0.f, sy = 0.f;
#pragma unroll
    for (int i = 0; i < 8; i++){ sx += red16[i]; sy += red16[i + 8]; }
    return make_float2(sx, sy);
}
__device__ __forceinline__ float blockRedSum_8w(float v, float* red16){
    int lane = threadIdx.x & 31, wid = threadIdx.x >> 5;
    __syncthreads();
    v = warpRedSum(v);
    if (lane == 0) red16[wid] = v;
    __syncthreads();
    float s = 0.f;
#pragma unroll
    for (int i = 0; i < 8; i++) s += red16[i];
    return s;
}
// exp(u) for tiny |u|: 4th-order Taylor, FMA-only
__device__ __forceinline__ float tiny_exp(float u){
    return 1.f + u * (1.f + u * (0.5f + u * (0.16666667f + u * 0.041666668f)));
}
__device__ __forceinline__ float sigmoidf(float z){
    return 1.f / (1.f + __expf(-z));
}

// ---------------- P0: merged prep — xT transpose + w->bf16 + g_r zero + setup ----------------
// Blocks [0, 12288): prep_x (b, c0, n0 decoded from index).
// Blocks [12288, 12288+864): prep_w + g_r zero; first of these also does setup.
#define PREPX_BLOCKS 12288
#define PREPW_BLOCKS 864

__global__ void __launch_bounds__(256) prep_kernel(const float* __restrict__ x,
                                                   const float* __restrict__ w,
                                                   const float* __restrict__ w_al,
                                                   const float* __restrict__ w_vl)
{
    const int tid = threadIdx.x;
    if (blockIdx.x < PREPX_BLOCKS){
        __shared__ float tile[32][33];
        const int idx = blockIdx.x;
        const int b  = idx / 1536;
        const int rem = idx % 1536;
        const int c0 = (rem >> 7) * 32;       // 12 c-tiles
        const int n0 = (rem & 127) * 32;      // 128 n-tiles
        const int lane = tid & 31, wg = tid >> 5;

#pragma unroll
        for (int r = 0; r < 4; r++){
            int c = wg + r * 8;
            tile[c][lane] = x[((size_t)b * C_ + c0 + c) * HW_ + n0 + lane];
        }
        __syncthreads();
#pragma unroll
        for (int r = 0; r < 4; r++){
            int i2 = tid + r * 256;
            int n = i2 >> 5, c = i2 & 31;
            g_xT[((size_t)b * HW_ + n0 + n) * C_ + c0 + c] = __float2bfloat16(tile[c][n]);
        }
        return;
    }

    const int wb = blockIdx.x - PREPX_BLOCKS;   // 0..863
    int gi = wb * 256 + tid;
    int i = gi * 2;                              // covers 442368 elems exactly
    {
        float2 v = *(const float2*)(w + i);
        *(__nv_bfloat162*)(g_wbf + i) = __floats2bfloat162_rn(v.x, v.y);
    }
    const int NR = B_ * HEADS_ * HW_;            // 262144
    const int stride = PREPW_BLOCKS * 256;
    for (int j = gi; j < NR; j += stride) g_r[j] = 0.f;

    if (wb == 0){
        __shared__ float avg[24];
        if (tid < 24){
            float s = 0.f;
            for (int d = 0; d < 48; d++) s += w_al[tid * 48 + d];
            avg[tid] = s * (1.f / 4096.f);
        }
        __syncthreads();
        if (tid == 0){
            float mx = -1e30f;
            for (int o = 0; o < 24; o++) mx = fmaxf(mx, avg[o]);
            float ssum = 0.f;
            for (int o = 0; o < 24; o++){ float ev = expf(avg[o] - mx); avg[o] = ev; ssum += ev; }
            float inv = 1.f / ssum;
            for (int o = 0; o < 24; o++) avg[o] *= inv;
        }
        __syncthreads();
        if (tid < 48){
            float s = 0.f;
            for (int o = 0; o < 24; o++) s += avg[o] * w_vl[o * 48 + tid];
            g_wv[tid] = s;
        }
        for (int j = tid; j < B_ * HEADS_ * D_; j += 256) g_vbar[j] = 0.f;
    }
}

// ---------------- P1: conv1x1 GEMM, bf16 mma.sync, 3-stage cp.async, upfront frags ----------------
__device__ __forceinline__ void mma16816(float* c, const uint32_t* a, const uint32_t* b){
    asm volatile(
        "mma.sync.aligned.m16n8k16.row.col.f32.bf16.bf16.f32 "
        "{%0,%1,%2,%3},{%4,%5,%6,%7},{%8,%9},{%0,%1,%2,%3};"
        : "+f"(c[0]), "+f"(c[1]), "+f"(c[2]), "+f"(c[3])
        : "r"(a[0]), "r"(a[1]), "r"(a[2]), "r"(a[3]), "r"(b[0]), "r"(b[1]));
}
__device__ __forceinline__ void ldsm_x4(uint32_t& r0, uint32_t& r1, uint32_t& r2, uint32_t& r3, uint32_t addr){
    asm volatile("ldmatrix.sync.aligned.m8n8.x4.shared.b16 {%0,%1,%2,%3},[%4];"
                 : "=r"(r0), "=r"(r1), "=r"(r2), "=r"(r3) : "r"(addr));
}
__device__ __forceinline__ void ldsm_x2(uint32_t& r0, uint32_t& r1, uint32_t addr){
    asm volatile("ldmatrix.sync.aligned.m8n8.x2.shared.b16 {%0,%1},[%2];"
                 : "=r"(r0), "=r"(r1) : "r"(addr));
}
__device__ __forceinline__ void cp16(uint32_t saddr, const void* gptr){
    asm volatile("cp.async.cg.shared.global [%0],[%1],16;" :: "r"(saddr), "l"(gptr));
}
__device__ __forceinline__ void cp_commit(){ asm volatile("cp.async.commit_group;"); }

#define GSTR 40                        // bf16 elems per smem row (32 data + pad)
#define STAGE_BYTES (128 * GSTR * 2)   // per matrix per stage = 10240 B
#define GSTAGES 3
#define GSMEM_TOTAL (GSTAGES * 2 * STAGE_BYTES)   // 61440 B

__global__ void __launch_bounds__(256) gemm_qkv_kernel()
{
    extern __shared__ __align__(128) __nv_bfloat16 gsm[];

    const int b  = blockIdx.z;
    const int o0 = blockIdx.y * 128;
    const int n0 = blockIdx.x * 128;
    const int tid  = threadIdx.x;
    const int warp = tid >> 5, lane = tid & 31;
    const int wm = (warp >> 2) * 64;
    const int wn = (warp & 3) * 32;

    float acc[4][4][4];
#pragma unroll
    for (int i = 0; i < 4; i++)
#pragma unroll
        for (int j = 0; j < 4; j++)
#pragma unroll
            for (int q = 0; q < 4; q++) acc[i][j][q] = 0.f;

    const __nv_bfloat16* wg = g_wbf + (size_t)o0 * C_;
    const __nv_bfloat16* xg = g_xT + ((size_t)b * HW_ + n0) * C_;

    const int r0i = (tid      ) >> 2, c0i = ((tid      ) & 3) * 8;
    const int r1i = (tid + 256) >> 2, c1i = ((tid + 256) & 3) * 8;

    const uint32_t sm0 = (uint32_t)__cvta_generic_to_shared(gsm);

    auto stage = [&](int c){
        uint32_t sa = sm0 + (c % GSTAGES) * 2 * STAGE_BYTES;
        uint32_t sb = sa + STAGE_BYTES;
        int k0 = c * 32;
        cp16(sa + (r0i * GSTR + c0i) * 2, wg + (size_t)r0i * C_ + k0 + c0i);
        cp16(sa + (r1i * GSTR + c1i) * 2, wg + (size_t)r1i * C_ + k0 + c1i);
        cp16(sb + (r0i * GSTR + c0i) * 2, xg + (size_t)r0i * C_ + k0 + c0i);
        cp16(sb + (r1i * GSTR + c1i) * 2, xg + (size_t)r1i * C_ + k0 + c1i);
        cp_commit();
    };

    stage(0); stage(1); stage(2);

    const int aRow = (lane & 7) + ((lane >> 3) & 1) * 8;
    const int aKof = (lane >> 4) * 8;
    const int bRow = (lane & 7);
    const int bKof = ((lane >> 3) & 1) * 8;

    for (int c = 0; c < 12; c++){
        if (c < 10)       asm volatile("cp.async.wait_group 2;");
        else if (c == 10) asm volatile("cp.async.wait_group 1;");
        else              asm volatile("cp.async.wait_group 0;");
        __syncthreads();

        uint32_t sa = sm0 + (c % GSTAGES) * 2 * STAGE_BYTES;
        uint32_t sb = sa + STAGE_BYTES;

#pragma unroll
        for (int kk = 0; kk < 2; kk++){
            const int krow = kk * 16;
            uint32_t af[4][4], bf[4][2];
#pragma unroll
            for (int mi = 0; mi < 4; mi++){
                uint32_t addr = sa + ((wm + mi * 16 + aRow) * GSTR + krow + aKof) * 2;
                ldsm_x4(af[mi][0], af[mi][1], af[mi][2], af[mi][3], addr);
            }
#pragma unroll
            for (int ni = 0; ni < 4; ni++){
                uint32_t addr = sb + ((wn + ni * 8 + bRow) * GSTR + krow + bKof) * 2;
                ldsm_x2(bf[ni][0], bf[ni][1], addr);
            }
#pragma unroll
            for (int mi = 0; mi < 4; mi++)
#pragma unroll
                for (int ni = 0; ni < 4; ni++)
                    mma16816(acc[mi][ni], af[mi], bf[ni]);
        }
        __syncthreads();
        if (c < 9) stage(c + 3);
    }

    __nv_bfloat16* out = g_pre + ((size_t)b * C3_ + o0) * HW_ + n0;
#pragma unroll
    for (int mi = 0; mi < 4; mi++){
#pragma unroll
        for (int ni = 0; ni < 4; ni++){
            int r = wm + mi * 16 + (lane >> 2);
            int c = wn + ni * 8 + (lane & 3) * 2;
            *(__nv_bfloat162*)(out + (size_t)r * HW_ + c) =
                __floats2bfloat162_rn(acc[mi][ni][0], acc[mi][ni][1]);
            *(__nv_bfloat162*)(out + (size_t)(r + 8) * HW_ + c) =
                __floats2bfloat162_rn(acc[mi][ni][2], acc[mi][ni][3]);
        }
    }
}

// ---------------- P2: fused dwconv(q,k,v) — single load phase, 5 syncs (R14 version) ----------------
// register-sliding 3x3 stencil: thread = column x, 16 outputs along y.
__device__ __forceinline__ float conv_col16(const float* tile, const float* w9,
                                            int x, int ys, float* o16)
{
    const float* tp = tile + ys * 66 + x;
    float a0 = tp[0],  a1 = tp[1],  a2 = tp[2];
    float b0 = tp[66], b1 = tp[67], b2 = tp[68];
    float ss = 0.f;
#pragma unroll
    for (int j = 0; j < 16; j++){
        const float* tr = tp + 132 + j * 66;
        float c0 = tr[0], c1 = tr[1], c2 = tr[2];
        float o = w9[0]*a0 + w9[1]*a1 + w9[2]*a2
                + w9[3]*b0 + w9[4]*b1 + w9[5]*b2
                + w9[6]*c0 + w9[7]*c1 + w9[8]*c2;
        o16[j] = o;
        ss = fmaf(o, o, ss);
        a0 = b0; a1 = b1; a2 = b2;
        b0 = c0; b1 = c1; b2 = c2;
    }
    return ss;
}

__global__ void __launch_bounds__(256) dwfuse_kernel(const float* __restrict__ w_dw,
                                                     const float* __restrict__ temp,
                                                     const float* __restrict__ w_ar)
{
    __shared__ float tiles[3][66 * 66];   // q, k, v
    __shared__ float red16[16];
    const int blk = blockIdx.x;           // b*384 + ch, ch = h*48 + d
    const int b = blk / 384, ch = blk % 384;
    const int h = ch / 48, dd = ch % 48;
    const int tid = threadIdx.x;
    const int x = tid & 63, ys = (tid >> 6) * 16;

    // ---- single load phase: halo zero + interior for all 3 planes ----
    if (tid < 66){
#pragma unroll
        for (int p = 0; p < 3; p++){ tiles[p][tid] = 0.f; tiles[p][65 * 66 + tid] = 0.f; }
    } else if (tid < 130){
        int yy = tid - 66;
#pragma unroll
        for (int p = 0; p < 3; p++){ tiles[p][(yy + 1) * 66] = 0.f; tiles[p][(yy + 1) * 66 + 65] = 0.f; }
    }
#pragma unroll
    for (int p = 0; p < 3; p++){
        const __nv_bfloat162* in2 = (const __nv_bfloat162*)
            (g_pre + ((size_t)b * C3_ + p * C_ + ch) * HW_);
        float* t = tiles[p];
#pragma unroll
        for (int q = tid; q < 2048; q += 256){
            int y = q >> 5, x0 = (q & 31) * 2;
            float2 f = __bfloat1622float2(in2[q]);
            t[(y + 1) * 66 + x0 + 1] = f.x;
            t[(y + 1) * 66 + x0 + 2] = f.y;
        }
    }
    __syncthreads();   // sync 1 of 5

    // ---- v plane: conv -> g_v (streamed, no sync) ----
    {
        float w9[9];
#pragma unroll
        for (int j = 0; j < 9; j++) w9[j] = __ldg(w_dw + (2 * C_ + ch) * 9 + j);
        const float* tp = tiles[2] + ys * 66 + x;
        float a0 = tp[0],  a1 = tp[1],  a2 = tp[2];
        float b0 = tp[66], b1 = tp[67], b2 = tp[68];
        __nv_bfloat16* outp = g_v + (size_t)blk * HW_ + ys * 64 + x;
#pragma unroll
        for (int j = 0; j < 16; j++){
            const float* tr = tp + 132 + j * 66;
            float c0 = tr[0], c1 = tr[1], c2 = tr[2];
            float o = w9[0]*a0 + w9[1]*a1 + w9[2]*a2
                    + w9[3]*b0 + w9[4]*b1 + w9[5]*b2
                    + w9[6]*c0 + w9[7]*c1 + w9[8]*c2;
            outp[j * 64] = __float2bfloat16(o);
            a0 = b0; a1 = b1; a2 = b2;
            b0 = c0; b1 = c1; b2 = c2;
        }
    }

    // ---- q, k planes: conv to registers ----
    float qv[16], kv[16];
    float ssq, ssk;
    {
        float w9[9];
#pragma unroll
        for (int j = 0; j < 9; j++) w9[j] = __ldg(w_dw + ch * 9 + j);
        ssq = conv_col16(tiles[0], w9, x, ys, qv);
#pragma unroll
        for (int j = 0; j < 9; j++) w9[j] = __ldg(w_dw + (C_ + ch) * 9 + j);
        ssk = conv_col16(tiles[1], w9, x, ys, kv);
    }

    float2 ns = blockRedSum2_8w(make_float2(ssq, ssk), red16);   // syncs 2-3
    const float nq = fmaxf(sqrtf(ns.x), 1e-12f);
    const float nk = fmaxf(sqrtf(ns.y), 1e-12f);
    const float scale = __ldg(temp + h) / (nq * nk);

    // e = exp(s), row sum S_d, then accumulate coef*e into g_r
    float zs = 0.f;
#pragma unroll
    for (int j = 0; j < 16; j++){
        float e = tiny_exp(qv[j] * kv[j] * scale);
        qv[j] = e;
        zs += e;
    }
    zs = blockRedSum_8w(zs, red16);                              // syncs 4-5
    const float coef = __ldg(w_ar + dd) / zs;

    float* rr = g_r + ((size_t)(b * HEADS_ + h)) * HW_ + ys * 64 + x;
#pragma unroll
    for (int j = 0; j < 16; j++)
        atomicAdd(rr + j * 64, coef * qv[j]);
}

// ---------------- P4: cmask = softmax_n(r), in place ----------------
__global__ void __launch_bounds__(512) softmax_r_kernel()
{
    __shared__ float red[32];
    const int bh = blockIdx.x, tid = threadIdx.x;
    float* r = g_r + (size_t)bh * HW_;

    float v[8];
    float m = -1e30f;
#pragma unroll
    for (int k = 0; k < 4; k++){
        float2 f = *(const float2*)(r + (tid + k * 512) * 2);
        v[2*k] = f.x; v[2*k+1] = f.y;
        m = fmaxf(m, fmaxf(f.x, f.y));
    }
    m = blockRedMax(m, red);
    float s = 0.f;
#pragma unroll
    for (int k = 0; k < 8; k++){ v[k] = __expf(v[k] - m); s += v[k]; }
    s = blockRedSum(s, red);
    const float inv = 1.f / s;
#pragma unroll
    for (int k = 0; k < 4; k++)
        *(float2*)(r + (tid + k * 512) * 2) = make_float2(v[2*k] * inv, v[2*k+1] * inv);
}

// ---------------- P5: vbar_d = sum_n cmask_n v_dn ; msp = sigmoid(sum_d wv_d v_dn) ----------------
// Grid (8, 64): 512 blocks, 512 n-cols each. Per-warp smem slots (no atomic contention).
__global__ void __launch_bounds__(256) vz_kernel()
{
    __shared__ float cm[512];
    __shared__ float wv_s[48];
    __shared__ float vsum[8 * 48];
    const int bh = blockIdx.y;
    const int n0 = blockIdx.x * 512;
    const int tid = threadIdx.x, lane = tid & 31, wid = tid >> 5;

    if (tid < 48) wv_s[tid] = g_wv[tid];
    *(float2*)(cm + tid * 2) = *(const float2*)(g_r + (size_t)bh * HW_ + n0 + tid * 2);
    __syncthreads();

    float zz0 = 0.f, zz1 = 0.f;
    const float c0 = cm[tid * 2], c1 = cm[tid * 2 + 1];
    const __nv_bfloat162* vb = (const __nv_bfloat162*)
        (g_v + ((size_t)bh * 48) * HW_ + n0);
    for (int d = 0; d < 48; d++){
        float2 f = __bfloat1622float2(vb[(size_t)d * (HW_ / 2) + tid]);
        const float wvd = wv_s[d];
        float dot = fmaf(c0, f.x, c1 * f.y);
        zz0 = fmaf(wvd, f.x, zz0);
        zz1 = fmaf(wvd, f.y, zz1);
        dot = warpRedSum(dot);
        if (lane == 0) vsum[wid * 48 + d] = dot;
    }
    __syncthreads();
    if (tid < 48){
        float s = 0.f;
#pragma unroll
        for (int w = 0; w < 8; w++) s += vsum[w * 48 + tid];
        atomicAdd(&g_vbar[bh * 48 + tid], s);
    }
    *(float2*)(g_msp + (size_t)bh * HW_ + n0 + tid * 2) =
        make_float2(sigmoidf(zz0), sigmoidf(zz1));
}

// ---------------- P6: ctx + MLP + LayerNorm -> channel gate ----------------
__global__ void __launch_bounds__(256) mlp_kernel(
    const float* __restrict__ w_vr,
    const float* __restrict__ w_up1, const float* __restrict__ b_up1,
    const float* __restrict__ ln_g,  const float* __restrict__ ln_b,
    const float* __restrict__ w_up2, const float* __restrict__ b_up2)
{
    __shared__ float vbar_s[384];
    __shared__ float ctx_s[192];
    __shared__ float t1[256];
    __shared__ float red[32];
    const int b = blockIdx.x, tid = threadIdx.x;

    for (int i = tid; i < 384; i += 256) vbar_s[i] = g_vbar[b * 384 + i];
    __syncthreads();
    if (tid < 192){
        int hh = tid / 24, o = tid % 24;
        float c = 0.f;
#pragma unroll
        for (int d = 0; d < 48; d++) c += w_vr[o * 48 + d] * vbar_s[hh * 48 + d];
        ctx_s[hh * 24 + o] = c;
    }
    __syncthreads();

    const int o = tid >> 3, hh = tid & 7;
    float t = b_up1[o];
#pragma unroll
    for (int p = 0; p < 24; p++) t += w_up1[o * 24 + p] * ctx_s[hh * 24 + p];

    float mu = blockRedSum(t, red) * (1.f / 256.f);
    float d = t - mu;
    float var = blockRedSum(d * d, red) * (1.f / 256.f);
    float tn = (t - mu) * rsqrtf(var + 1e-5f) * ln_g[o * 8 + hh] + ln_b[o * 8 + hh];
    t1[tid] = fmaxf(tn, 0.f);
    __syncthreads();

    for (int idx = tid; idx < 384; idx += 256){
        int dd = idx >> 3, h2 = idx & 7;
        float v = b_up2[dd];
#pragma unroll
        for (int oo = 0; oo < 32; oo++) v += w_up2[dd * 32 + oo] * t1[oo * 8 + h2];
        g_mch[b * 384 + dd * 8 + h2] = sigmoidf(v);
    }
}

// ---------------- P7: out = x * (mch[b,c] + sum_h w_proj[c,h]*msp[b,h,n]) ----------------
// Grid (16,4,8): block = 256 n-cols x 96 channels; msp in registers (1 col/thread).
__global__ void __launch_bounds__(256) final_kernel(
    const float* __restrict__ x, const float* __restrict__ w_proj,
    float* __restrict__ out)
{
    __shared__ float wp_s[96 * 8];
    __shared__ float mch_s[96];
    const int b  = blockIdx.z;
    const int n0 = blockIdx.x * 256;
    const int c0 = blockIdx.y * 96;
    const int tid = threadIdx.x;
    const int nn = n0 + tid;

    // msp for this thread's column, all 8 heads -> registers (coalesced LDG)
    float mh[8];
#pragma unroll
    for (int h = 0; h < 8; h++)
        mh[h] = g_msp[((size_t)(b * 8 + h)) * HW_ + nn];

    for (int i = tid; i < 768; i += 256) wp_s[i] = w_proj[c0 * 8 + i];
    if (tid < 96) mch_s[tid] = g_mch[b * 384 + c0 + tid];
    __syncthreads();

    for (int cc = 0; cc < 96; cc++){
        const float* wp = wp_s + cc * 8;
        float a = mch_s[cc];
#pragma unroll
        for (int h = 0; h < 8; h++) a = fmaf(wp[h], mh[h], a);
        size_t base = ((size_t)(b * 384 + c0 + cc)) * HW_ + nn;
        out[base] = x[base] * a;
    }
}

// ---------------- launcher ----------------
extern "C" void kernel_launch(void* const* d_in, const int* in_sizes, int n_in,
                              void* d_out, int out_size)
{
    const float* x      = (const float*)d_in[0];
    const float* w_qkv  = (const float*)d_in[1];
    const float* w_dw   = (const float*)d_in[2];
    const float* temp   = (const float*)d_in[3];
    const float* w_ar   = (const float*)d_in[4];
    const float* w_vr   = (const float*)d_in[5];
    const float* w_up1  = (const float*)d_in[6];
    const float* b_up1  = (const float*)d_in[7];
    const float* ln_g   = (const float*)d_in[8];
    const float* ln_b   = (const float*)d_in[9];
    const float* w_up2  = (const float*)d_in[10];
    const float* b_up2  = (const float*)d_in[11];
    const float* w_al   = (const float*)d_in[12];
    const float* w_vl   = (const float*)d_in[13];
    const float* w_proj = (const float*)d_in[14];
    float* out = (float*)d_out;

    cudaFuncSetAttribute(gemm_qkv_kernel,
                         cudaFuncAttributeMaxDynamicSharedMemorySize, GSMEM_TOTAL);

    prep_kernel<<<PREPX_BLOCKS + PREPW_BLOCKS, 256>>>(x, w_qkv, w_al, w_vl);
    gemm_qkv_kernel<<<dim3(32, 9, 8), 256, GSMEM_TOTAL>>>();
    dwfuse_kernel<<<B_ * C_, 256>>>(w_dw, temp, w_ar);
    softmax_r_kernel<<<64, 512>>>();
    vz_kernel<<<dim3(8, 64), 256>>>();
    mlp_kernel<<<B_, 256>>>(w_vr, w_up1, b_up1, ln_g, ln_b, w_up2, b_up2);
    final_kernel<<<dim3(16, 4, 8), 256>>>(x, w_proj, out);
}

// round 17
// speedup vs baseline: 1.0616x; 1.0123x over previous
#include <cuda_runtime.h>
#include <cuda_bf16.h>
#include <stdint.h>
#include <math.h>

// ---------------- problem constants ----------------
#define B_    8
#define C_    384
#define C3_   1152
#define HW_   4096
#define HEADS_ 8
#define D_    48
#define DH_   24
#define D2_   32

// ---------------- device scratch ----------------
__device__ __align__(128) __nv_bfloat16  g_pre [(size_t)B_*C3_*HW_];   // qkv pre-dwconv (bf16)
__device__ __align__(128) __nv_bfloat16  g_v   [(size_t)B_*C_*HW_];    // v after dwconv (bf16)
__device__ __align__(128) __nv_bfloat16  g_wbf [C3_*C_];               // w_qkv in bf16
__device__ __align__(128) __nv_bfloat16  g_xT  [(size_t)B_*HW_*C_];    // x transposed [b,n,c] bf16
__device__ __align__(16) float g_r   [(size_t)B_*HEADS_*HW_];// r accum -> cmask (1MB)
__device__ float          g_wv  [D_];                   // avg_x @ w_vl (constant)
__device__ float          g_vbar[B_*HEADS_*D_];
__device__ __align__(16) float g_msp [(size_t)B_*HEADS_*HW_];
__device__ float          g_mch [B_*C_];

// ---------------- helpers ----------------
__device__ __forceinline__ float warpRedSum(float v){
#pragma unroll
    for (int o = 16; o > 0; o >>= 1) v += __shfl_xor_sync(0xffffffffu, v, o);
    return v;
}
__device__ __forceinline__ float warpRedMax(float v){
#pragma unroll
    for (int o = 16; o > 0; o >>= 1) v = fmaxf(v, __shfl_xor_sync(0xffffffffu, v, o));
    return v;
}
__device__ __forceinline__ float blockRedSum(float v, float* red){
    int tid = threadIdx.x, lane = tid & 31, wid = tid >> 5, nw = blockDim.x >> 5;
    __syncthreads();
    v = warpRedSum(v);
    if (lane == 0) red[wid] = v;
    __syncthreads();
    float r = (tid < nw) ? red[tid] : 0.f;
    if (wid == 0) r = warpRedSum(r);
    if (tid == 0) red[0] = r;
    __syncthreads();
    return red[0];
}
__device__ __forceinline__ float blockRedMax(float v, float* red){
    int tid = threadIdx.x, lane = tid & 31, wid = tid >> 5, nw = blockDim.x >> 5;
    __syncthreads();
    v = warpRedMax(v);
    if (lane == 0) red[wid] = v;
    __syncthreads();
    float r = (tid < nw) ? red[tid] : -1e30f;
    if (wid == 0) r = warpRedMax(r);
    if (tid == 0) red[0] = r;
    __syncthreads();
    return red[0];
}
// lean reductions for 8-warp (256-thread) blocks: 2 syncs each
__device__ __forceinline__ float2 blockRedSum2_8w(float2 v, float* red16){
    int lane = threadIdx.x & 31, wid = threadIdx.x >> 5;
    __syncthreads();
#pragma unroll
    for (int o = 16; o > 0; o >>= 1){
        v.x += __shfl_xor_sync(0xffffffffu, v.x, o);
        v.y += __shfl_xor_sync(0xffffffffu, v.y, o);
    }
    if (lane == 0){ red16[wid] = v.x; red16[wid + 8] = v.y; }
    __syncthreads();
    float sx = 0.f, sy = 0.f;
#pragma unroll
    for (int i = 0; i < 8; i++){ sx += red16[i]; sy += red16[i + 8]; }
    return make_float2(sx, sy);
}
__device__ __forceinline__ float blockRedSum_8w(float v, float* red16){
    int lane = threadIdx.x & 31, wid = threadIdx.x >> 5;
    __syncthreads();
    v = warpRedSum(v);
    if (lane == 0) red16[wid] = v;
    __syncthreads();
    float s = 0.f;
#pragma unroll
    for (int i = 0; i < 8; i++) s += red16[i];
    return s;
}
// exp(u) for tiny |u|: 4th-order Taylor, FMA-only
__device__ __forceinline__ float tiny_exp(float u){
    return 1.f + u * (1.f + u * (0.5f + u * (0.16666667f + u * 0.041666668f)));
}
__device__ __forceinline__ float sigmoidf(float z){
    return 1.f / (1.f + __expf(-z));
}

// ---------------- P0: merged prep — xT transpose + w->bf16 + g_r zero + setup ----------------
#define PREPX_BLOCKS 12288
#define PREPW_BLOCKS 864

__global__ void __launch_bounds__(256) prep_kernel(const float* __restrict__ x,
                                                   const float* __restrict__ w,
                                                   const float* __restrict__ w_al,
                                                   const float* __restrict__ w_vl)
{
    const int tid = threadIdx.x;
    if (blockIdx.x < PREPX_BLOCKS){
        __shared__ float tile[32][33];
        const int idx = blockIdx.x;
        const int b  = idx / 1536;
        const int rem = idx % 1536;
        const int c0 = (rem >> 7) * 32;       // 12 c-tiles
        const int n0 = (rem & 127) * 32;      // 128 n-tiles
        const int lane = tid & 31, wg = tid >> 5;

#pragma unroll
        for (int r = 0; r < 4; r++){
            int c = wg + r * 8;
            tile[c][lane] = x[((size_t)b * C_ + c0 + c) * HW_ + n0 + lane];
        }
        __syncthreads();
#pragma unroll
        for (int r = 0; r < 4; r++){
            int i2 = tid + r * 256;
            int n = i2 >> 5, c = i2 & 31;
            g_xT[((size_t)b * HW_ + n0 + n) * C_ + c0 + c] = __float2bfloat16(tile[c][n]);
        }
        return;
    }

    const int wb = blockIdx.x - PREPX_BLOCKS;   // 0..863
    int gi = wb * 256 + tid;
    int i = gi * 2;                              // covers 442368 elems exactly
    {
        float2 v = *(const float2*)(w + i);
        *(__nv_bfloat162*)(g_wbf + i) = __floats2bfloat162_rn(v.x, v.y);
    }
    const int NR = B_ * HEADS_ * HW_;            // 262144
    const int stride = PREPW_BLOCKS * 256;
    for (int j = gi; j < NR; j += stride) g_r[j] = 0.f;

    if (wb == 0){
        __shared__ float avg[24];
        if (tid < 24){
            float s = 0.f;
            for (int d = 0; d < 48; d++) s += w_al[tid * 48 + d];
            avg[tid] = s * (1.f / 4096.f);
        }
        __syncthreads();
        if (tid == 0){
            float mx = -1e30f;
            for (int o = 0; o < 24; o++) mx = fmaxf(mx, avg[o]);
            float ssum = 0.f;
            for (int o = 0; o < 24; o++){ float ev = expf(avg[o] - mx); avg[o] = ev; ssum += ev; }
            float inv = 1.f / ssum;
            for (int o = 0; o < 24; o++) avg[o] *= inv;
        }
        __syncthreads();
        if (tid < 48){
            float s = 0.f;
            for (int o = 0; o < 24; o++) s += avg[o] * w_vl[o * 48 + tid];
            g_wv[tid] = s;
        }
        for (int j = tid; j < B_ * HEADS_ * D_; j += 256) g_vbar[j] = 0.f;
    }
}

// ---------------- P1: conv1x1 GEMM — 64-wide k-chunks, 3-stage cp.async ----------------
__device__ __forceinline__ void mma16816(float* c, const uint32_t* a, const uint32_t* b){
    asm volatile(
        "mma.sync.aligned.m16n8k16.row.col.f32.bf16.bf16.f32 "
        "{%0,%1,%2,%3},{%4,%5,%6,%7},{%8,%9},{%0,%1,%2,%3};"
        : "+f"(c[0]), "+f"(c[1]), "+f"(c[2]), "+f"(c[3])
        : "r"(a[0]), "r"(a[1]), "r"(a[2]), "r"(a[3]), "r"(b[0]), "r"(b[1]));
}
__device__ __forceinline__ void ldsm_x4(uint32_t& r0, uint32_t& r1, uint32_t& r2, uint32_t& r3, uint32_t addr){
    asm volatile("ldmatrix.sync.aligned.m8n8.x4.shared.b16 {%0,%1,%2,%3},[%4];"
                 : "=r"(r0), "=r"(r1), "=r"(r2), "=r"(r3) : "r"(addr));
}
__device__ __forceinline__ void ldsm_x2(uint32_t& r0, uint32_t& r1, uint32_t addr){
    asm volatile("ldmatrix.sync.aligned.m8n8.x2.shared.b16 {%0,%1},[%2];"
                 : "=r"(r0), "=r"(r1) : "r"(addr));
}
__device__ __forceinline__ void cp16(uint32_t saddr, const void* gptr){
    asm volatile("cp.async.cg.shared.global [%0],[%1],16;" :: "r"(saddr), "l"(gptr));
}
__device__ __forceinline__ void cp_commit(){ asm volatile("cp.async.commit_group;"); }

#define GSTR 72                        // bf16 elems per smem row (64 data + pad); 144B rows
#define STAGE_BYTES (128 * GSTR * 2)   // per matrix per stage = 18432 B
#define GSTAGES 3
#define GSMEM_TOTAL (GSTAGES * 2 * STAGE_BYTES)   // 110592 B

__global__ void __launch_bounds__(256) gemm_qkv_kernel()
{
    extern __shared__ __align__(128) __nv_bfloat16 gsm[];

    const int b  = blockIdx.z;
    const int o0 = blockIdx.y * 128;
    const int n0 = blockIdx.x * 128;
    const int tid  = threadIdx.x;
    const int warp = tid >> 5, lane = tid & 31;
    const int wm = (warp >> 2) * 64;
    const int wn = (warp & 3) * 32;

    float acc[4][4][4];
#pragma unroll
    for (int i = 0; i < 4; i++)
#pragma unroll
        for (int j = 0; j < 4; j++)
#pragma unroll
            for (int q = 0; q < 4; q++) acc[i][j][q] = 0.f;

    const __nv_bfloat16* wg = g_wbf + (size_t)o0 * C_;
    const __nv_bfloat16* xg = g_xT + ((size_t)b * HW_ + n0) * C_;

    const uint32_t sm0 = (uint32_t)__cvta_generic_to_shared(gsm);

    // stage 64 k-cols: 1024 16B-units per matrix, 4 per thread per matrix
    auto stage = [&](int c){
        uint32_t sa = sm0 + (c % GSTAGES) * 2 * STAGE_BYTES;
        uint32_t sb = sa + STAGE_BYTES;
        int k0 = c * 64;
#pragma unroll
        for (int m = 0; m < 4; m++){
            int u = tid + m * 256;              // 0..1023
            int r = u >> 3, c16 = (u & 7) * 8;  // row 0..127, col elem 0..56
            cp16(sa + (r * GSTR + c16) * 2, wg + (size_t)r * C_ + k0 + c16);
            cp16(sb + (r * GSTR + c16) * 2, xg + (size_t)r * C_ + k0 + c16);
        }
        cp_commit();
    };

    stage(0); stage(1); stage(2);

    const int aRow = (lane & 7) + ((lane >> 3) & 1) * 8;
    const int aKof = (lane >> 4) * 8;
    const int bRow = (lane & 7);
    const int bKof = ((lane >> 3) & 1) * 8;

    for (int c = 0; c < 6; c++){
        if (c < 4)       asm volatile("cp.async.wait_group 2;");
        else if (c == 4) asm volatile("cp.async.wait_group 1;");
        else             asm volatile("cp.async.wait_group 0;");
        __syncthreads();

        uint32_t sa = sm0 + (c % GSTAGES) * 2 * STAGE_BYTES;
        uint32_t sb = sa + STAGE_BYTES;

#pragma unroll
        for (int kk = 0; kk < 4; kk++){
            const int krow = kk * 16;
            uint32_t af[4][4], bf[4][2];
#pragma unroll
            for (int mi = 0; mi < 4; mi++){
                uint32_t addr = sa + ((wm + mi * 16 + aRow) * GSTR + krow + aKof) * 2;
                ldsm_x4(af[mi][0], af[mi][1], af[mi][2], af[mi][3], addr);
            }
#pragma unroll
            for (int ni = 0; ni < 4; ni++){
                uint32_t addr = sb + ((wn + ni * 8 + bRow) * GSTR + krow + bKof) * 2;
                ldsm_x2(bf[ni][0], bf[ni][1], addr);
            }
#pragma unroll
            for (int mi = 0; mi < 4; mi++)
#pragma unroll
                for (int ni = 0; ni < 4; ni++)
                    mma16816(acc[mi][ni], af[mi], bf[ni]);
        }
        __syncthreads();
        if (c < 3) stage(c + 3);
    }

    __nv_bfloat16* out = g_pre + ((size_t)b * C3_ + o0) * HW_ + n0;
#pragma unroll
    for (int mi = 0; mi < 4; mi++){
#pragma unroll
        for (int ni = 0; ni < 4; ni++){
            int r = wm + mi * 16 + (lane >> 2);
            int c = wn + ni * 8 + (lane & 3) * 2;
            *(__nv_bfloat162*)(out + (size_t)r * HW_ + c) =
                __floats2bfloat162_rn(acc[mi][ni][0], acc[mi][ni][1]);
            *(__nv_bfloat162*)(out + (size_t)(r + 8) * HW_ + c) =
                __floats2bfloat162_rn(acc[mi][ni][2], acc[mi][ni][3]);
        }
    }
}

// ---------------- P2: fused dwconv(q,k,v) — single load phase, 5 syncs (locked R14) ----------------
__device__ __forceinline__ float conv_col16(const float* tile, const float* w9,
                                            int x, int ys, float* o16)
{
    const float* tp = tile + ys * 66 + x;
    float a0 = tp[0],  a1 = tp[1],  a2 = tp[2];
    float b0 = tp[66], b1 = tp[67], b2 = tp[68];
    float ss = 0.f;
#pragma unroll
    for (int j = 0; j < 16; j++){
        const float* tr = tp + 132 + j * 66;
        float c0 = tr[0], c1 = tr[1], c2 = tr[2];
        float o = w9[0]*a0 + w9[1]*a1 + w9[2]*a2
                + w9[3]*b0 + w9[4]*b1 + w9[5]*b2
                + w9[6]*c0 + w9[7]*c1 + w9[8]*c2;
        o16[j] = o;
        ss = fmaf(o, o, ss);
        a0 = b0; a1 = b1; a2 = b2;
        b0 = c0; b1 = c1; b2 = c2;
    }
    return ss;
}

__global__ void __launch_bounds__(256) dwfuse_kernel(const float* __restrict__ w_dw,
                                                     const float* __restrict__ temp,
                                                     const float* __restrict__ w_ar)
{
    __shared__ float tiles[3][66 * 66];   // q, k, v
    __shared__ float red16[16];
    const int blk = blockIdx.x;           // b*384 + ch, ch = h*48 + d
    const int b = blk / 384, ch = blk % 384;
    const int h = ch / 48, dd = ch % 48;
    const int tid = threadIdx.x;
    const int x = tid & 63, ys = (tid >> 6) * 16;

    if (tid < 66){
#pragma unroll
        for (int p = 0; p < 3; p++){ tiles[p][tid] = 0.f; tiles[p][65 * 66 + tid] = 0.f; }
    } else if (tid < 130){
        int yy = tid - 66;
#pragma unroll
        for (int p = 0; p < 3; p++){ tiles[p][(yy + 1) * 66] = 0.f; tiles[p][(yy + 1) * 66 + 65] = 0.f; }
    }
#pragma unroll
    for (int p = 0; p < 3; p++){
        const __nv_bfloat162* in2 = (const __nv_bfloat162*)
            (g_pre + ((size_t)b * C3_ + p * C_ + ch) * HW_);
        float* t = tiles[p];
#pragma unroll
        for (int q = tid; q < 2048; q += 256){
            int y = q >> 5, x0 = (q & 31) * 2;
            float2 f = __bfloat1622float2(in2[q]);
            t[(y + 1) * 66 + x0 + 1] = f.x;
            t[(y + 1) * 66 + x0 + 2] = f.y;
        }
    }
    __syncthreads();   // sync 1 of 5

    // ---- v plane ----
    {
        float w9[9];
#pragma unroll
        for (int j = 0; j < 9; j++) w9[j] = __ldg(w_dw + (2 * C_ + ch) * 9 + j);
        const float* tp = tiles[2] + ys * 66 + x;
        float a0 = tp[0],  a1 = tp[1],  a2 = tp[2];
        float b0 = tp[66], b1 = tp[67], b2 = tp[68];
        __nv_bfloat16* outp = g_v + (size_t)blk * HW_ + ys * 64 + x;
#pragma unroll
        for (int j = 0; j < 16; j++){
            const float* tr = tp + 132 + j * 66;
            float c0 = tr[0], c1 = tr[1], c2 = tr[2];
            float o = w9[0]*a0 + w9[1]*a1 + w9[2]*a2
                    + w9[3]*b0 + w9[4]*b1 + w9[5]*b2
                    + w9[6]*c0 + w9[7]*c1 + w9[8]*c2;
            outp[j * 64] = __float2bfloat16(o);
            a0 = b0; a1 = b1; a2 = b2;
            b0 = c0; b1 = c1; b2 = c2;
        }
    }

    // ---- q, k planes ----
    float qv[16], kv[16];
    float ssq, ssk;
    {
        float w9[9];
#pragma unroll
        for (int j = 0; j < 9; j++) w9[j] = __ldg(w_dw + ch * 9 + j);
        ssq = conv_col16(tiles[0], w9, x, ys, qv);
#pragma unroll
        for (int j = 0; j < 9; j++) w9[j] = __ldg(w_dw + (C_ + ch) * 9 + j);
        ssk = conv_col16(tiles[1], w9, x, ys, kv);
    }

    float2 ns = blockRedSum2_8w(make_float2(ssq, ssk), red16);   // syncs 2-3
    const float nq = fmaxf(sqrtf(ns.x), 1e-12f);
    const float nk = fmaxf(sqrtf(ns.y), 1e-12f);
    const float scale = __ldg(temp + h) / (nq * nk);

    float zs = 0.f;
#pragma unroll
    for (int j = 0; j < 16; j++){
        float e = tiny_exp(qv[j] * kv[j] * scale);
        qv[j] = e;
        zs += e;
    }
    zs = blockRedSum_8w(zs, red16);                              // syncs 4-5
    const float coef = __ldg(w_ar + dd) / zs;

    float* rr = g_r + ((size_t)(b * HEADS_ + h)) * HW_ + ys * 64 + x;
#pragma unroll
    for (int j = 0; j < 16; j++)
        atomicAdd(rr + j * 64, coef * qv[j]);
}

// ---------------- P4: cmask = softmax_n(r), in place ----------------
__global__ void __launch_bounds__(512) softmax_r_kernel()
{
    __shared__ float red[32];
    const int bh = blockIdx.x, tid = threadIdx.x;
    float* r = g_r + (size_t)bh * HW_;

    float v[8];
    float m = -1e30f;
#pragma unroll
    for (int k = 0; k < 4; k++){
        float2 f = *(const float2*)(r + (tid + k * 512) * 2);
        v[2*k] = f.x; v[2*k+1] = f.y;
        m = fmaxf(m, fmaxf(f.x, f.y));
    }
    m = blockRedMax(m, red);
    float s = 0.f;
#pragma unroll
    for (int k = 0; k < 8; k++){ v[k] = __expf(v[k] - m); s += v[k]; }
    s = blockRedSum(s, red);
    const float inv = 1.f / s;
#pragma unroll
    for (int k = 0; k < 4; k++)
        *(float2*)(r + (tid + k * 512) * 2) = make_float2(v[2*k] * inv, v[2*k+1] * inv);
}

// ---------------- P5: vz — per-warp smem slots (locked R16) ----------------
__global__ void __launch_bounds__(256) vz_kernel()
{
    __shared__ float cm[512];
    __shared__ float wv_s[48];
    __shared__ float vsum[8 * 48];
    const int bh = blockIdx.y;
    const int n0 = blockIdx.x * 512;
    const int tid = threadIdx.x, lane = tid & 31, wid = tid >> 5;

    if (tid < 48) wv_s[tid] = g_wv[tid];
    *(float2*)(cm + tid * 2) = *(const float2*)(g_r + (size_t)bh * HW_ + n0 + tid * 2);
    __syncthreads();

    float zz0 = 0.f, zz1 = 0.f;
    const float c0 = cm[tid * 2], c1 = cm[tid * 2 + 1];
    const __nv_bfloat162* vb = (const __nv_bfloat162*)
        (g_v + ((size_t)bh * 48) * HW_ + n0);
    for (int d = 0; d < 48; d++){
        float2 f = __bfloat1622float2(vb[(size_t)d * (HW_ / 2) + tid]);
        const float wvd = wv_s[d];
        float dot = fmaf(c0, f.x, c1 * f.y);
        zz0 = fmaf(wvd, f.x, zz0);
        zz1 = fmaf(wvd, f.y, zz1);
        dot = warpRedSum(dot);
        if (lane == 0) vsum[wid * 48 + d] = dot;
    }
    __syncthreads();
    if (tid < 48){
        float s = 0.f;
#pragma unroll
        for (int w = 0; w < 8; w++) s += vsum[w * 48 + tid];
        atomicAdd(&g_vbar[bh * 48 + tid], s);
    }
    *(float2*)(g_msp + (size_t)bh * HW_ + n0 + tid * 2) =
        make_float2(sigmoidf(zz0), sigmoidf(zz1));
}

// ---------------- P6: ctx + MLP + LayerNorm -> channel gate ----------------
__global__ void __launch_bounds__(256) mlp_kernel(
    const float* __restrict__ w_vr,
    const float* __restrict__ w_up1, const float* __restrict__ b_up1,
    const float* __restrict__ ln_g,  const float* __restrict__ ln_b,
    const float* __restrict__ w_up2, const float* __restrict__ b_up2)
{
    __shared__ float vbar_s[384];
    __shared__ float ctx_s[192];
    __shared__ float t1[256];
    __shared__ float red[32];
    const int b = blockIdx.x, tid = threadIdx.x;

    for (int i = tid; i < 384; i += 256) vbar_s[i] = g_vbar[b * 384 + i];
    __syncthreads();
    if (tid < 192){
        int hh = tid / 24, o = tid % 24;
        float c = 0.f;
#pragma unroll
        for (int d = 0; d < 48; d++) c += w_vr[o * 48 + d] * vbar_s[hh * 48 + d];
        ctx_s[hh * 24 + o] = c;
    }
    __syncthreads();

    const int o = tid >> 3, hh = tid & 7;
    float t = b_up1[o];
#pragma unroll
    for (int p = 0; p < 24; p++) t += w_up1[o * 24 + p] * ctx_s[hh * 24 + p];

    float mu = blockRedSum(t, red) * (1.f / 256.f);
    float d = t - mu;
    float var = blockRedSum(d * d, red) * (1.f / 256.f);
    float tn = (t - mu) * rsqrtf(var + 1e-5f) * ln_g[o * 8 + hh] + ln_b[o * 8 + hh];
    t1[tid] = fmaxf(tn, 0.f);
    __syncthreads();

    for (int idx = tid; idx < 384; idx += 256){
        int dd = idx >> 3, h2 = idx & 7;
        float v = b_up2[dd];
#pragma unroll
        for (int oo = 0; oo < 32; oo++) v += w_up2[dd * 32 + oo] * t1[oo * 8 + h2];
        g_mch[b * 384 + dd * 8 + h2] = sigmoidf(v);
    }
}

// ---------------- P7: out gate — grid (16,8,8): 256 n-cols x 48 channels per block ----------------
__global__ void __launch_bounds__(256) final_kernel(
    const float* __restrict__ x, const float* __restrict__ w_proj,
    float* __restrict__ out)
{
    __shared__ float wp_s[48 * 8];
    __shared__ float mch_s[48];
    const int b  = blockIdx.z;
    const int n0 = blockIdx.x * 256;
    const int c0 = blockIdx.y * 48;
    const int tid = threadIdx.x;
    const int nn = n0 + tid;

    float mh[8];
#pragma unroll
    for (int h = 0; h < 8; h++)
        mh[h] = g_msp[((size_t)(b * 8 + h)) * HW_ + nn];

    if (tid < 48) mch_s[tid] = g_mch[b * 384 + c0 + tid];
    else if (tid >= 64 && tid < 64 + 48 * 8 / 2){
        int i = (tid - 64) * 2;
        *(float2*)(wp_s + i) = *(const float2*)(w_proj + c0 * 8 + i);
    }
    __syncthreads();

    for (int cc = 0; cc < 48; cc++){
        const float* wp = wp_s + cc * 8;
        float a = mch_s[cc];
#pragma unroll
        for (int h = 0; h < 8; h++) a = fmaf(wp[h], mh[h], a);
        size_t base = ((size_t)(b * 384 + c0 + cc)) * HW_ + nn;
        out[base] = x[base] * a;
    }
}

// ---------------- launcher ----------------
extern "C" void kernel_launch(void* const* d_in, const int* in_sizes, int n_in,
                              void* d_out, int out_size)
{
    const float* x      = (const float*)d_in[0];
    const float* w_qkv  = (const float*)d_in[1];
    const float* w_dw   = (const float*)d_in[2];
    const float* temp   = (const float*)d_in[3];
    const float* w_ar   = (const float*)d_in[4];
    const float* w_vr   = (const float*)d_in[5];
    const float* w_up1  = (const float*)d_in[6];
    const float* b_up1  = (const float*)d_in[7];
    const float* ln_g   = (const float*)d_in[8];
    const float* ln_b   = (const float*)d_in[9];
    const float* w_up2  = (const float*)d_in[10];
    const float* b_up2  = (const float*)d_in[11];
    const float* w_al   = (const float*)d_in[12];
    const float* w_vl   = (const float*)d_in[13];
    const float* w_proj = (const float*)d_in[14];
    float* out = (float*)d_out;

    cudaFuncSetAttribute(gemm_qkv_kernel,
                         cudaFuncAttributeMaxDynamicSharedMemorySize, GSMEM_TOTAL);

    prep_kernel<<<PREPX_BLOCKS + PREPW_BLOCKS, 256>>>(x, w_qkv, w_al, w_vl);
    gemm_qkv_kernel<<<dim3(32, 9, 8), 256, GSMEM_TOTAL>>>();
    dwfuse_kernel<<<B_ * C_, 256>>>(w_dw, temp, w_ar);
    softmax_r_kernel<<<64, 512>>>();
    vz_kernel<<<dim3(8, 64), 256>>>();
    mlp_kernel<<<B_, 256>>>(w_vr, w_up1, b_up1, ln_g, ln_b, w_up2, b_up2);
    final_kernel<<<dim3(16, 8, 8), 256>>>(x, w_proj, out);
}